// round 7
// baseline (speedup 1.0000x reference)
#include <cuda_runtime.h>
#include <cstdint>

#define HH 128
#define NPAD 100096          // = 782*128
#define EMAX 1600000
#define NTH 256
#define SCAN_B 512

// ---------------- scratch ----------------
__device__ float g_xp [NPAD * HH];
__device__ float g_acc[NPAD * HH];     // MEAN-aggregated features
__device__ float g_h  [NPAD * HH];
__device__ float g_xp0[NPAD * 2];
__device__ int   g_deg [NPAD];
__device__ int   g_off [NPAD + 1];
__device__ int   g_cur [NPAD];
__device__ int   g_srcs[EMAX];
__device__ int   g_bsum [4096];
__device__ int   g_bsumx[4096];

__device__ __forceinline__ float warp_sum(float v) {
#pragma unroll
    for (int o = 16; o > 0; o >>= 1) v += __shfl_xor_sync(0xffffffffu, v, o);
    return v;
}
__device__ __forceinline__ float quad_sum(float v) {
    v += __shfl_xor_sync(0xffffffffu, v, 1);
    v += __shfl_xor_sync(0xffffffffu, v, 2);
    return v;
}
__device__ __forceinline__ uint32_t f2tf(float f) {
    uint32_t r;
    asm("cvt.rna.tf32.f32 %0, %1;" : "=r"(r) : "f"(f));
    return r;
}
// split x into tf32 hi + tf32 lo (3xTF32 emulated-fp32)
__device__ __forceinline__ void tfsplit(float x, uint32_t& hi, uint32_t& lo) {
    hi = f2tf(x);
    lo = f2tf(x - __uint_as_float(hi));
}
__device__ __forceinline__ void cp16(void* dst, const void* src) {
    uint32_t d = (uint32_t)__cvta_generic_to_shared(dst);
    asm volatile("cp.async.ca.shared.global [%0], [%1], 16;" :: "r"(d), "l"(src));
}
#define CP_COMMIT() asm volatile("cp.async.commit_group;")
#define CP_WAIT0()  asm volatile("cp.async.wait_group 0;" ::: "memory")

#define MMA_TF32(d, a0v, a1v, a2v, a3v, b0v, b1v)                                \
    asm volatile(                                                                \
        "mma.sync.aligned.m16n8k8.row.col.f32.tf32.tf32.f32 "                    \
        "{%0,%1,%2,%3}, {%4,%5,%6,%7}, {%8,%9}, {%0,%1,%2,%3};"                  \
        : "+f"(d[0]), "+f"(d[1]), "+f"(d[2]), "+f"(d[3])                         \
        : "r"(a0v), "r"(a1v), "r"(a2v), "r"(a3v), "r"(b0v), "r"(b1v))

// ================= CSR build =================
__global__ void k_hist(const int* __restrict__ ei, int E) {
    int e = blockIdx.x * blockDim.x + threadIdx.x;
    if (e >= E) return;
    atomicAdd(&g_deg[ei[E + e]], 1);
}
__global__ void __launch_bounds__(SCAN_B) k_scan1(int n) {
    __shared__ int sm[SCAN_B];
    int t = threadIdx.x;
    int idx = blockIdx.x * SCAN_B + t;
    int v = (idx < n) ? g_deg[idx] : 0;
    sm[t] = v;
    __syncthreads();
#pragma unroll
    for (int off = 1; off < SCAN_B; off <<= 1) {
        int add = (t >= off) ? sm[t - off] : 0;
        __syncthreads();
        sm[t] += add;
        __syncthreads();
    }
    if (idx < n) g_off[idx] = sm[t] - v;
    if (t == SCAN_B - 1) g_bsum[blockIdx.x] = sm[t];
}
__global__ void __launch_bounds__(1024) k_scan2(int nb) {
    __shared__ int sm[1024];
    int t = threadIdx.x;
    int v = (t < nb) ? g_bsum[t] : 0;
    sm[t] = v;
    __syncthreads();
#pragma unroll
    for (int off = 1; off < 1024; off <<= 1) {
        int add = (t >= off) ? sm[t - off] : 0;
        __syncthreads();
        sm[t] += add;
        __syncthreads();
    }
    if (t < nb) g_bsumx[t] = sm[t] - v;
}
__global__ void k_scan3(int n, int E) {
    int idx = blockIdx.x * blockDim.x + threadIdx.x;
    if (idx == 0) g_off[n] = E;
    if (idx >= n) return;
    int o = g_off[idx] + g_bsumx[idx / SCAN_B];
    g_off[idx] = o;
    g_cur[idx] = o;
}
__global__ void k_scatter(const int* __restrict__ ei, int E) {
    int e = blockIdx.x * blockDim.x + threadIdx.x;
    if (e >= E) return;
    int s = ei[e], d = ei[E + e];
    int pos = atomicAdd(&g_cur[d], 1);
    g_srcs[pos] = s;
}

// ================= layer 0 =================
__global__ void k_l0(const float* __restrict__ x, const float* __restrict__ Wp,
                     const float* __restrict__ bp, int n) {
    int i = blockIdx.x * blockDim.x + threadIdx.x;
    if (i >= n) return;
    float x0 = x[2 * i], x1 = x[2 * i + 1];
    float a = fmaxf(fmaf(x0, Wp[0], fmaf(x1, Wp[2], bp[0])), 0.f);
    float b = fmaxf(fmaf(x0, Wp[1], fmaf(x1, Wp[3], bp[1])), 0.f);
    g_xp0[2 * i] = a;
    g_xp0[2 * i + 1] = b;
}

__global__ void __launch_bounds__(256) k_combine0(int n, const float* __restrict__ Wl,
        const float* __restrict__ bl, const float* __restrict__ Wr,
        const float* __restrict__ lnw, const float* __restrict__ lnb) {
    int node = (blockIdx.x * 256 + threadIdx.x) >> 5;
    int lane = threadIdx.x & 31;
    if (node >= n) return;
    int beg = g_off[node], end = g_off[node + 1];
    float m0 = 0.f, m1 = 0.f;
    for (int j = beg + lane; j < end; j += 32) {
        int s = __ldg(&g_srcs[j]);
        float2 v = *(const float2*)&g_xp0[2 * s];
        m0 += v.x; m1 += v.y;
    }
    m0 = warp_sum(m0); m1 = warp_sum(m1);
    float inv = 1.f / fmaxf((float)(end - beg), 1.f);
    m0 *= inv; m1 *= inv;
    float p0 = g_xp0[2 * node], p1 = g_xp0[2 * node + 1];
    float v[4]; float s = 0.f;
#pragma unroll
    for (int k = 0; k < 4; k++) {
        int c = lane + 32 * k;
        v[k] = fmaf(m0, Wl[c], fmaf(m1, Wl[HH + c],
               fmaf(p0, Wr[c], fmaf(p1, Wr[HH + c], bl[c]))));
        s += v[k];
    }
    s = warp_sum(s);
    float mu = s * (1.f / HH);
    float q = 0.f;
#pragma unroll
    for (int k = 0; k < 4; k++) { v[k] -= mu; q += v[k] * v[k]; }
    q = warp_sum(q);
    float rstd = rsqrtf(q * (1.f / HH) + 1e-5f);
    size_t base = (size_t)node * HH;
#pragma unroll
    for (int k = 0; k < 4; k++) {
        int c = lane + 32 * k;
        g_h[base + c] = v[k] * rstd * lnw[c] + lnb[c];
    }
}

// ================= heavy aggregation: CSR gather-reduce, warp per node =================
__global__ void __launch_bounds__(256) k_gagg(int n) {
    int node = (blockIdx.x * 256 + threadIdx.x) >> 5;
    int lane = threadIdx.x & 31;
    if (node >= n) return;
    int beg = g_off[node], end = g_off[node + 1];
    float4 a = make_float4(0.f, 0.f, 0.f, 0.f);
    int j = beg;
    for (; j + 2 <= end; j += 2) {
        int s0 = __ldg(&g_srcs[j]);
        int s1 = __ldg(&g_srcs[j + 1]);
        float4 v0 = *(const float4*)&g_xp[(size_t)s0 * HH + lane * 4];
        float4 v1 = *(const float4*)&g_xp[(size_t)s1 * HH + lane * 4];
        a.x += v0.x + v1.x; a.y += v0.y + v1.y;
        a.z += v0.z + v1.z; a.w += v0.w + v1.w;
    }
    if (j < end) {
        int s0 = __ldg(&g_srcs[j]);
        float4 v0 = *(const float4*)&g_xp[(size_t)s0 * HH + lane * 4];
        a.x += v0.x; a.y += v0.y; a.z += v0.z; a.w += v0.w;
    }
    float inv = 1.f / fmaxf((float)(end - beg), 1.f);
    a.x *= inv; a.y *= inv; a.z *= inv; a.w *= inv;
    *(float4*)&g_acc[(size_t)node * HH + lane * 4] = a;
}

// =================== 3xTF32 MMA GEMM core ===================
// CTA tile 128x128, 8 warps, warp tile 16x128. Each input is split
// hi/lo; accumulate hi*hi + hi*lo + lo*hi for ~fp32 accuracy.
// As[2][128][20]  m-major; Ws[2][16][136] k-major (pad 8).

#define GEMM_DECLS                                                            \
    const int t = threadIdx.x;                                                \
    const int warp = t >> 5, lane = t & 31;                                   \
    const int g = lane >> 2, q = lane & 3;                                    \
    const int mrow = warp * 16;                                               \
    const int ar = t >> 1, aoff = (t & 1) * 8;                                \
    const int wr = t >> 4, woff = (t & 15) * 8;                               \
    float c[16][4];                                                           \
    _Pragma("unroll")                                                         \
    for (int j = 0; j < 16; j++)                                              \
        _Pragma("unroll")                                                     \
        for (int u = 0; u < 4; u++) c[j][u] = 0.f;

#define STAGE_W(buf, Wptr)                                                    \
    {                                                                         \
        cp16(&Ws[buf][wr][woff],     (Wptr) + (size_t)wr * HH + woff);        \
        cp16(&Ws[buf][wr][woff + 4], (Wptr) + (size_t)wr * HH + woff + 4);    \
    }
#define STAGE_A(buf, Aptr)                                                    \
    {                                                                         \
        cp16(&As[buf][ar][aoff],     (Aptr) + aoff);                          \
        cp16(&As[buf][ar][aoff + 4], (Aptr) + aoff + 4);                      \
    }

#define GEMM_COMPUTE(cur)                                                     \
    _Pragma("unroll")                                                         \
    for (int kk = 0; kk < 2; kk++) {                                          \
        uint32_t ah[4], al[4];                                                \
        tfsplit(As[cur][mrow + g][kk * 8 + q],          ah[0], al[0]);        \
        tfsplit(As[cur][mrow + g + 8][kk * 8 + q],      ah[1], al[1]);        \
        tfsplit(As[cur][mrow + g][kk * 8 + q + 4],      ah[2], al[2]);        \
        tfsplit(As[cur][mrow + g + 8][kk * 8 + q + 4],  ah[3], al[3]);        \
        _Pragma("unroll")                                                     \
        for (int j = 0; j < 16; j++) {                                        \
            uint32_t bh[2], bl_[2];                                           \
            tfsplit(Ws[cur][kk * 8 + q][8 * j + g],     bh[0], bl_[0]);       \
            tfsplit(Ws[cur][kk * 8 + q + 4][8 * j + g], bh[1], bl_[1]);       \
            MMA_TF32(c[j], ah[0], ah[1], ah[2], ah[3], bl_[0], bl_[1]);       \
            MMA_TF32(c[j], al[0], al[1], al[2], al[3], bh[0], bh[1]);         \
            MMA_TF32(c[j], ah[0], ah[1], ah[2], ah[3], bh[0], bh[1]);         \
        }                                                                     \
    }

// ---------------- proj GEMM: xp = relu(h @ Wp + bp) ----------------
__global__ void __launch_bounds__(NTH, 2) k_proj(const float* __restrict__ W,
                                                 const float* __restrict__ bias) {
    __shared__ float As[2][128][20];
    __shared__ float Ws[2][16][136];
    GEMM_DECLS
    const int row0 = blockIdx.x * 128;
    const float* Arow = &g_h[(size_t)(row0 + ar) * HH];

    STAGE_A(0, Arow); STAGE_W(0, W); CP_COMMIT();
    const int NT = HH / 16;  // 8
#pragma unroll
    for (int it = 0; it < NT; it++) {
        int cur = it & 1;
        CP_WAIT0();
        __syncthreads();
        if (it + 1 < NT) {
            int k0 = (it + 1) * 16;
            STAGE_A(cur ^ 1, Arow + k0);
            STAGE_W(cur ^ 1, W + (size_t)k0 * HH);
            CP_COMMIT();
        }
        GEMM_COMPUTE(cur)
    }

    int r0 = row0 + mrow + g, r1 = r0 + 8;
#pragma unroll
    for (int j = 0; j < 16; j++) {
        int jc = 8 * j + 2 * q;
        float2 bv = *(const float2*)&bias[jc];
        float2 o0, o1;
        o0.x = fmaxf(c[j][0] + bv.x, 0.f); o0.y = fmaxf(c[j][1] + bv.y, 0.f);
        o1.x = fmaxf(c[j][2] + bv.x, 0.f); o1.y = fmaxf(c[j][3] + bv.y, 0.f);
        *(float2*)&g_xp[(size_t)r0 * HH + jc] = o0;
        *(float2*)&g_xp[(size_t)r1 * HH + jc] = o1;
    }
}

// ---------------- combine GEMM (K=256: mean | xp) + fused LN ----------------
__global__ void __launch_bounds__(NTH, 2) k_combine(const float* __restrict__ Wl,
        const float* __restrict__ Wr, const float* __restrict__ bl,
        const float* __restrict__ lnw, const float* __restrict__ lnb) {
    __shared__ float As[2][128][20];
    __shared__ float Ws[2][16][136];
    GEMM_DECLS
    const int row0 = blockIdx.x * 128;
    const float* Aa = &g_acc[(size_t)(row0 + ar) * HH];
    const float* Ax = &g_xp[(size_t)(row0 + ar) * HH];

    STAGE_A(0, Aa); STAGE_W(0, Wl); CP_COMMIT();
    const int NT = 16;
#pragma unroll
    for (int it = 0; it < NT; it++) {
        int cur = it & 1;
        CP_WAIT0();
        __syncthreads();
        if (it + 1 < NT) {
            int nx = it + 1;
            const float* Ap = (nx < 8) ? (Aa + nx * 16) : (Ax + (nx - 8) * 16);
            const float* Wn = (nx < 8) ? (Wl + (size_t)nx * 16 * HH)
                                       : (Wr + (size_t)(nx - 8) * 16 * HH);
            STAGE_A(cur ^ 1, Ap);
            STAGE_W(cur ^ 1, Wn);
            CP_COMMIT();
        }
        GEMM_COMPUTE(cur)
    }

    float sl = 0.f, sh = 0.f;
#pragma unroll
    for (int j = 0; j < 16; j++) {
        int jc = 8 * j + 2 * q;
        float2 bv = *(const float2*)&bl[jc];
        c[j][0] += bv.x; c[j][1] += bv.y;
        c[j][2] += bv.x; c[j][3] += bv.y;
        sl += c[j][0] + c[j][1];
        sh += c[j][2] + c[j][3];
    }
    sl = quad_sum(sl); sh = quad_sum(sh);
    float mul = sl * (1.f / HH), muh = sh * (1.f / HH);
    float ql = 0.f, qh = 0.f;
#pragma unroll
    for (int j = 0; j < 16; j++) {
        c[j][0] -= mul; c[j][1] -= mul; c[j][2] -= muh; c[j][3] -= muh;
        ql += c[j][0] * c[j][0] + c[j][1] * c[j][1];
        qh += c[j][2] * c[j][2] + c[j][3] * c[j][3];
    }
    ql = quad_sum(ql); qh = quad_sum(qh);
    float rl = rsqrtf(ql * (1.f / HH) + 1e-5f);
    float rh = rsqrtf(qh * (1.f / HH) + 1e-5f);
    int r0 = row0 + mrow + g, r1 = r0 + 8;
#pragma unroll
    for (int j = 0; j < 16; j++) {
        int jc = 8 * j + 2 * q;
        float2 lw = *(const float2*)&lnw[jc];
        float2 lb = *(const float2*)&lnb[jc];
        float2 o0, o1;
        o0.x = c[j][0] * rl * lw.x + lb.x; o0.y = c[j][1] * rl * lw.y + lb.y;
        o1.x = c[j][2] * rh * lw.x + lb.x; o1.y = c[j][3] * rh * lw.y + lb.y;
        *(float2*)&g_h[(size_t)r0 * HH + jc] = o0;
        *(float2*)&g_h[(size_t)r1 * HH + jc] = o1;
    }
}

// ---------------- edge MLP: gather-GEMM (K=256) + fused W2 reduction ----------------
__global__ void __launch_bounds__(NTH, 2) k_edgemlp(const int* __restrict__ eli, int Q,
        const float* __restrict__ W1, const float* __restrict__ b1,
        const float* __restrict__ W2, const float* __restrict__ b2,
        float* __restrict__ out) {
    __shared__ float As[2][128][20];
    __shared__ float Ws[2][16][136];
    __shared__ int sbase[128], dbase[128];
    GEMM_DECLS
    const int q0 = blockIdx.x * 128;

    if (t < 128) {
        int qq = q0 + t, s = 0, d = 0;
        if (qq < Q) { s = eli[qq]; d = eli[Q + qq]; }
        sbase[t] = s * HH; dbase[t] = d * HH;
    }
    __syncthreads();
    const float* Asrc = &g_h[(size_t)sbase[ar]];
    const float* Adst = &g_h[(size_t)dbase[ar]];

    STAGE_A(0, Asrc); STAGE_W(0, W1); CP_COMMIT();
    const int NT = 16;
#pragma unroll
    for (int it = 0; it < NT; it++) {
        int cur = it & 1;
        CP_WAIT0();
        __syncthreads();
        if (it + 1 < NT) {
            int nx = it + 1;
            const float* Ap = (nx < 8) ? (Asrc + nx * 16) : (Adst + (nx - 8) * 16);
            STAGE_A(cur ^ 1, Ap);
            STAGE_W(cur ^ 1, W1 + (size_t)nx * 16 * HH);
            CP_COMMIT();
        }
        GEMM_COMPUTE(cur)
    }

    float sl = 0.f, sh = 0.f;
#pragma unroll
    for (int j = 0; j < 16; j++) {
        int jc = 8 * j + 2 * q;
        float2 bv = *(const float2*)&b1[jc];
        float2 wv = *(const float2*)&W2[jc];
        sl = fmaf(fmaxf(c[j][0] + bv.x, 0.f), wv.x, sl);
        sl = fmaf(fmaxf(c[j][1] + bv.y, 0.f), wv.y, sl);
        sh = fmaf(fmaxf(c[j][2] + bv.x, 0.f), wv.x, sh);
        sh = fmaf(fmaxf(c[j][3] + bv.y, 0.f), wv.y, sh);
    }
    sl = quad_sum(sl); sh = quad_sum(sh);
    if (q == 0) {
        float b2v = b2[0];
        int r0 = q0 + mrow + g, r1 = r0 + 8;
        if (r0 < Q) out[r0] = sl + b2v;
        if (r1 < Q) out[r1] = sh + b2v;
    }
}

// ---------------- host launch ----------------
extern "C" void kernel_launch(void* const* d_in, const int* in_sizes, int n_in,
                              void* d_out, int out_size) {
    const float* x    = (const float*)d_in[0];
    const int*   ei   = (const int*)d_in[1];
    const int*   eli  = (const int*)d_in[2];
    const float* p0Wp = (const float*)d_in[3];
    const float* p0bp = (const float*)d_in[4];
    const float* p0Wl = (const float*)d_in[5];
    const float* p0bl = (const float*)d_in[6];
    const float* p0Wr = (const float*)d_in[7];
    const float* Wp_s = (const float*)d_in[8];
    const float* bp_s = (const float*)d_in[9];
    const float* Wl_s = (const float*)d_in[10];
    const float* bl_s = (const float*)d_in[11];
    const float* Wr_s = (const float*)d_in[12];
    const float* ln_w = (const float*)d_in[13];
    const float* ln_b = (const float*)d_in[14];
    const float* eW1  = (const float*)d_in[15];
    const float* eb1  = (const float*)d_in[16];
    const float* eW2  = (const float*)d_in[17];
    const float* eb2  = (const float*)d_in[18];
    float* out = (float*)d_out;

    const int n = in_sizes[0] / 2;
    const int E = in_sizes[1] / 2;
    const int Q = in_sizes[2] / 2;

    // ---- CSR build (once) ----
    void* degp = nullptr;
    cudaGetSymbolAddress(&degp, g_deg);
    cudaMemsetAsync(degp, 0, (size_t)n * sizeof(int));
    k_hist<<<(E + 255) / 256, 256>>>(ei, E);
    const int nb = (n + SCAN_B - 1) / SCAN_B;
    k_scan1<<<nb, SCAN_B>>>(n);
    k_scan2<<<1, 1024>>>(nb);
    k_scan3<<<(n + 255) / 256, 256>>>(n, E);
    k_scatter<<<(E + 255) / 256, 256>>>(ei, E);

    // ---- layer 0 ----
    k_l0<<<(n + 255) / 256, 256>>>(x, p0Wp, p0bp, n);
    k_combine0<<<(n * 32 + 255) / 256, 256>>>(n, p0Wl, p0bl, p0Wr, ln_w, ln_b);

    // ---- layers 1..2 ----
    const int gb = (n + 127) / 128;   // 782
    const int gaggB = (n * 32 + 255) / 256;
    for (int l = 0; l < 2; l++) {
        k_proj<<<gb, NTH>>>(Wp_s + (size_t)l * HH * HH, bp_s + (size_t)l * HH);
        k_gagg<<<gaggB, 256>>>(n);
        k_combine<<<gb, NTH>>>(Wl_s + (size_t)l * HH * HH, Wr_s + (size_t)l * HH * HH,
                               bl_s + (size_t)l * HH,
                               ln_w + (size_t)(l + 1) * HH, ln_b + (size_t)(l + 1) * HH);
    }
    k_edgemlp<<<(Q + 127) / 128, NTH>>>(eli, Q, eW1, eb1, eW2, eb2, out);
}

// round 8
// speedup vs baseline: 1.0265x; 1.0265x over previous
#include <cuda_runtime.h>
#include <cstdint>

#define HH 128
#define NPAD 100096          // = 782*128
#define EMAX 1600000
#define NTH 256
#define SCAN_B 512

// ---------------- scratch ----------------
__device__ float g_xp [NPAD * HH];
__device__ float g_acc[NPAD * HH];     // MEAN-aggregated features
__device__ float g_h  [NPAD * HH];
__device__ float g_xp0[NPAD * 2];
__device__ int   g_deg [NPAD];
__device__ int   g_off [NPAD + 1];
__device__ int   g_cur [NPAD];
__device__ int   g_srcs[EMAX];
__device__ int   g_bsum [4096];
__device__ int   g_bsumx[4096];

__device__ __forceinline__ float warp_sum(float v) {
#pragma unroll
    for (int o = 16; o > 0; o >>= 1) v += __shfl_xor_sync(0xffffffffu, v, o);
    return v;
}
__device__ __forceinline__ float quad_sum(float v) {
    v += __shfl_xor_sync(0xffffffffu, v, 1);
    v += __shfl_xor_sync(0xffffffffu, v, 2);
    return v;
}
__device__ __forceinline__ uint32_t f2tf(float f) {
    uint32_t r;
    asm("cvt.rna.tf32.f32 %0, %1;" : "=r"(r) : "f"(f));
    return r;
}

#define MMA_TF32(d, a0v, a1v, a2v, a3v, b0v, b1v)                                \
    asm volatile(                                                                \
        "mma.sync.aligned.m16n8k8.row.col.f32.tf32.tf32.f32 "                    \
        "{%0,%1,%2,%3}, {%4,%5,%6,%7}, {%8,%9}, {%0,%1,%2,%3};"                  \
        : "+f"(d[0]), "+f"(d[1]), "+f"(d[2]), "+f"(d[3])                         \
        : "r"(a0v), "r"(a1v), "r"(a2v), "r"(a3v), "r"(b0v), "r"(b1v))

// ================= CSR build =================
__global__ void k_hist(const int* __restrict__ ei, int E) {
    int e = blockIdx.x * blockDim.x + threadIdx.x;
    if (e >= E) return;
    atomicAdd(&g_deg[ei[E + e]], 1);
}
__global__ void __launch_bounds__(SCAN_B) k_scan1(int n) {
    __shared__ int sm[SCAN_B];
    int t = threadIdx.x;
    int idx = blockIdx.x * SCAN_B + t;
    int v = (idx < n) ? g_deg[idx] : 0;
    sm[t] = v;
    __syncthreads();
#pragma unroll
    for (int off = 1; off < SCAN_B; off <<= 1) {
        int add = (t >= off) ? sm[t - off] : 0;
        __syncthreads();
        sm[t] += add;
        __syncthreads();
    }
    if (idx < n) g_off[idx] = sm[t] - v;
    if (t == SCAN_B - 1) g_bsum[blockIdx.x] = sm[t];
}
__global__ void __launch_bounds__(1024) k_scan2(int nb) {
    __shared__ int sm[1024];
    int t = threadIdx.x;
    int v = (t < nb) ? g_bsum[t] : 0;
    sm[t] = v;
    __syncthreads();
#pragma unroll
    for (int off = 1; off < 1024; off <<= 1) {
        int add = (t >= off) ? sm[t - off] : 0;
        __syncthreads();
        sm[t] += add;
        __syncthreads();
    }
    if (t < nb) g_bsumx[t] = sm[t] - v;
}
__global__ void k_scan3(int n, int E) {
    int idx = blockIdx.x * blockDim.x + threadIdx.x;
    if (idx == 0) g_off[n] = E;
    if (idx >= n) return;
    int o = g_off[idx] + g_bsumx[idx / SCAN_B];
    g_off[idx] = o;
    g_cur[idx] = o;
}
__global__ void k_scatter(const int* __restrict__ ei, int E) {
    int e = blockIdx.x * blockDim.x + threadIdx.x;
    if (e >= E) return;
    int s = ei[e], d = ei[E + e];
    int pos = atomicAdd(&g_cur[d], 1);
    g_srcs[pos] = s;
}

// ================= layer 0 =================
__global__ void k_l0(const float* __restrict__ x, const float* __restrict__ Wp,
                     const float* __restrict__ bp, int n) {
    int i = blockIdx.x * blockDim.x + threadIdx.x;
    if (i >= n) return;
    float x0 = x[2 * i], x1 = x[2 * i + 1];
    float a = fmaxf(fmaf(x0, Wp[0], fmaf(x1, Wp[2], bp[0])), 0.f);
    float b = fmaxf(fmaf(x0, Wp[1], fmaf(x1, Wp[3], bp[1])), 0.f);
    g_xp0[2 * i] = a;
    g_xp0[2 * i + 1] = b;
}

__global__ void __launch_bounds__(256) k_combine0(int n, const float* __restrict__ Wl,
        const float* __restrict__ bl, const float* __restrict__ Wr,
        const float* __restrict__ lnw, const float* __restrict__ lnb) {
    int node = (blockIdx.x * 256 + threadIdx.x) >> 5;
    int lane = threadIdx.x & 31;
    if (node >= n) return;
    int beg = g_off[node], end = g_off[node + 1];
    float m0 = 0.f, m1 = 0.f;
    for (int j = beg + lane; j < end; j += 32) {
        int s = __ldg(&g_srcs[j]);
        float2 v = *(const float2*)&g_xp0[2 * s];
        m0 += v.x; m1 += v.y;
    }
    m0 = warp_sum(m0); m1 = warp_sum(m1);
    float inv = 1.f / fmaxf((float)(end - beg), 1.f);
    m0 *= inv; m1 *= inv;
    float p0 = g_xp0[2 * node], p1 = g_xp0[2 * node + 1];
    float v[4]; float s = 0.f;
#pragma unroll
    for (int k = 0; k < 4; k++) {
        int c = lane + 32 * k;
        v[k] = fmaf(m0, Wl[c], fmaf(m1, Wl[HH + c],
               fmaf(p0, Wr[c], fmaf(p1, Wr[HH + c], bl[c]))));
        s += v[k];
    }
    s = warp_sum(s);
    float mu = s * (1.f / HH);
    float q = 0.f;
#pragma unroll
    for (int k = 0; k < 4; k++) { v[k] -= mu; q += v[k] * v[k]; }
    q = warp_sum(q);
    float rstd = rsqrtf(q * (1.f / HH) + 1e-5f);
    size_t base = (size_t)node * HH;
#pragma unroll
    for (int k = 0; k < 4; k++) {
        int c = lane + 32 * k;
        g_h[base + c] = v[k] * rstd * lnw[c] + lnb[c];
    }
}

// ================= heavy aggregation: CSR gather-reduce, warp per node =================
__global__ void __launch_bounds__(256) k_gagg(int n) {
    int node = (blockIdx.x * 256 + threadIdx.x) >> 5;
    int lane = threadIdx.x & 31;
    if (node >= n) return;
    int beg = g_off[node], end = g_off[node + 1];
    float4 a = make_float4(0.f, 0.f, 0.f, 0.f);
    int j = beg;
    for (; j + 2 <= end; j += 2) {
        int s0 = __ldg(&g_srcs[j]);
        int s1 = __ldg(&g_srcs[j + 1]);
        float4 v0 = *(const float4*)&g_xp[(size_t)s0 * HH + lane * 4];
        float4 v1 = *(const float4*)&g_xp[(size_t)s1 * HH + lane * 4];
        a.x += v0.x + v1.x; a.y += v0.y + v1.y;
        a.z += v0.z + v1.z; a.w += v0.w + v1.w;
    }
    if (j < end) {
        int s0 = __ldg(&g_srcs[j]);
        float4 v0 = *(const float4*)&g_xp[(size_t)s0 * HH + lane * 4];
        a.x += v0.x; a.y += v0.y; a.z += v0.z; a.w += v0.w;
    }
    float inv = 1.f / fmaxf((float)(end - beg), 1.f);
    a.x *= inv; a.y *= inv; a.z *= inv; a.w *= inv;
    *(float4*)&g_acc[(size_t)node * HH + lane * 4] = a;
}

// =================== 3xTF32 MMA GEMM core (hoisted split) ===================
// CTA tile 128x128, 8 warps, warp tile 16x128, k-stage = 8, double buffered.
// hi/lo tf32 split done ONCE at staging; smem holds interleaved (hi,lo) pairs.
// As[2][128][24]: row=m, col=2k+{0 hi,1 lo}; stride 24 floats -> conflict-free
//                 half-warp LDS.64 fragment reads (banks partition 8/8/8/8).
// Ws[2][8][264]:  row=k(0..7), col=2n+{0,1}; stride 264 = 8 mod 32 banks.
// Staging: LDG float4 -> split -> 2x STS.128.

#define GEMM_DECLS                                                            \
    const int t = threadIdx.x;                                                \
    const int warp = t >> 5, lane = t & 31;                                   \
    const int g = lane >> 2, q = lane & 3;                                    \
    const int mrow = warp * 16;                                               \
    const int ar = t >> 1, aoff = (t & 1) * 4;                                \
    const int wr = t >> 5, wcol = (t & 31) * 4;                               \
    float4 pa, pw;                                                            \
    float c[16][4];                                                           \
    _Pragma("unroll")                                                         \
    for (int j = 0; j < 16; j++)                                              \
        _Pragma("unroll")                                                     \
        for (int u = 0; u < 4; u++) c[j][u] = 0.f;

// split float4 v into (hi,lo) pairs and store 32B at dst
#define SPLIT_STS(v, dst)                                                     \
    {                                                                         \
        float h0 = __uint_as_float(f2tf(v.x));                                \
        float h1 = __uint_as_float(f2tf(v.y));                                \
        float h2 = __uint_as_float(f2tf(v.z));                                \
        float h3 = __uint_as_float(f2tf(v.w));                                \
        float4 o0, o1;                                                        \
        o0.x = h0; o0.y = v.x - h0; o0.z = h1; o0.w = v.y - h1;               \
        o1.x = h2; o1.y = v.z - h2; o1.z = h3; o1.w = v.w - h3;               \
        ((float4*)(dst))[0] = o0; ((float4*)(dst))[1] = o1;                   \
    }

#define STAGE(buf)                                                            \
    {                                                                         \
        SPLIT_STS(pa, &As[buf][ar][2 * aoff]);                                \
        SPLIT_STS(pw, &Ws[buf][wr][2 * wcol]);                                \
    }

#define GEMM_COMPUTE(cur)                                                     \
    {                                                                         \
        float2 a0 = *(const float2*)&As[cur][mrow + g][2 * q];                \
        float2 a1 = *(const float2*)&As[cur][mrow + g + 8][2 * q];            \
        float2 a2 = *(const float2*)&As[cur][mrow + g][2 * (q + 4)];          \
        float2 a3 = *(const float2*)&As[cur][mrow + g + 8][2 * (q + 4)];      \
        uint32_t ah0 = __float_as_uint(a0.x), al0 = __float_as_uint(a0.y);    \
        uint32_t ah1 = __float_as_uint(a1.x), al1 = __float_as_uint(a1.y);    \
        uint32_t ah2 = __float_as_uint(a2.x), al2 = __float_as_uint(a2.y);    \
        uint32_t ah3 = __float_as_uint(a3.x), al3 = __float_as_uint(a3.y);    \
        _Pragma("unroll")                                                     \
        for (int j = 0; j < 16; j++) {                                        \
            float2 b0 = *(const float2*)&Ws[cur][q][2 * (8 * j + g)];         \
            float2 b1 = *(const float2*)&Ws[cur][q + 4][2 * (8 * j + g)];     \
            uint32_t bh0 = __float_as_uint(b0.x), bl0 = __float_as_uint(b0.y);\
            uint32_t bh1 = __float_as_uint(b1.x), bl1 = __float_as_uint(b1.y);\
            MMA_TF32(c[j], ah0, ah1, ah2, ah3, bl0, bl1);                     \
            MMA_TF32(c[j], al0, al1, al2, al3, bh0, bh1);                     \
            MMA_TF32(c[j], ah0, ah1, ah2, ah3, bh0, bh1);                     \
        }                                                                     \
    }

// ---------------- proj GEMM: xp = relu(h @ Wp + bp) ----------------
__global__ void __launch_bounds__(NTH, 2) k_proj(const float* __restrict__ W,
                                                 const float* __restrict__ bias) {
    __shared__ float As[2][128][24];
    __shared__ float Ws[2][8][264];
    GEMM_DECLS
    const int row0 = blockIdx.x * 128;
    const float* Arow = &g_h[(size_t)(row0 + ar) * HH];

    pa = *(const float4*)(Arow + aoff);
    pw = *(const float4*)&W[(size_t)wr * HH + wcol];
    STAGE(0);

    const int NT = HH / 8;  // 16
#pragma unroll 2
    for (int it = 0; it < NT; it++) {
        int cur = it & 1;
        __syncthreads();
        if (it + 1 < NT) {
            int k0 = (it + 1) * 8;
            pa = *(const float4*)(Arow + k0 + aoff);
            pw = *(const float4*)&W[(size_t)(k0 + wr) * HH + wcol];
        }
        GEMM_COMPUTE(cur)
        if (it + 1 < NT) STAGE(cur ^ 1);
    }

    int r0 = row0 + mrow + g, r1 = r0 + 8;
#pragma unroll
    for (int j = 0; j < 16; j++) {
        int jc = 8 * j + 2 * q;
        float2 bv = *(const float2*)&bias[jc];
        float2 o0, o1;
        o0.x = fmaxf(c[j][0] + bv.x, 0.f); o0.y = fmaxf(c[j][1] + bv.y, 0.f);
        o1.x = fmaxf(c[j][2] + bv.x, 0.f); o1.y = fmaxf(c[j][3] + bv.y, 0.f);
        *(float2*)&g_xp[(size_t)r0 * HH + jc] = o0;
        *(float2*)&g_xp[(size_t)r1 * HH + jc] = o1;
    }
}

// ---------------- combine GEMM (K=256: mean | xp) + fused LN ----------------
__global__ void __launch_bounds__(NTH, 2) k_combine(const float* __restrict__ Wl,
        const float* __restrict__ Wr, const float* __restrict__ bl,
        const float* __restrict__ lnw, const float* __restrict__ lnb) {
    __shared__ float As[2][128][24];
    __shared__ float Ws[2][8][264];
    GEMM_DECLS
    const int row0 = blockIdx.x * 128;
    const float* Aa = &g_acc[(size_t)(row0 + ar) * HH];
    const float* Ax = &g_xp[(size_t)(row0 + ar) * HH];

    pa = *(const float4*)(Aa + aoff);
    pw = *(const float4*)&Wl[(size_t)wr * HH + wcol];
    STAGE(0);

    const int NT = 32;  // K=256 / 8
#pragma unroll 2
    for (int it = 0; it < NT; it++) {
        int cur = it & 1;
        __syncthreads();
        if (it + 1 < NT) {
            int nx = it + 1;
            const float* Ap;
            const float* Wn;
            if (nx < 16) { Ap = Aa + nx * 8; Wn = Wl + (size_t)nx * 8 * HH; }
            else         { Ap = Ax + (nx - 16) * 8; Wn = Wr + (size_t)(nx - 16) * 8 * HH; }
            pa = *(const float4*)(Ap + aoff);
            pw = *(const float4*)&Wn[(size_t)wr * HH + wcol];
        }
        GEMM_COMPUTE(cur)
        if (it + 1 < NT) STAGE(cur ^ 1);
    }

    float sl = 0.f, sh = 0.f;
#pragma unroll
    for (int j = 0; j < 16; j++) {
        int jc = 8 * j + 2 * q;
        float2 bv = *(const float2*)&bl[jc];
        c[j][0] += bv.x; c[j][1] += bv.y;
        c[j][2] += bv.x; c[j][3] += bv.y;
        sl += c[j][0] + c[j][1];
        sh += c[j][2] + c[j][3];
    }
    sl = quad_sum(sl); sh = quad_sum(sh);
    float mul = sl * (1.f / HH), muh = sh * (1.f / HH);
    float ql = 0.f, qh = 0.f;
#pragma unroll
    for (int j = 0; j < 16; j++) {
        c[j][0] -= mul; c[j][1] -= mul; c[j][2] -= muh; c[j][3] -= muh;
        ql += c[j][0] * c[j][0] + c[j][1] * c[j][1];
        qh += c[j][2] * c[j][2] + c[j][3] * c[j][3];
    }
    ql = quad_sum(ql); qh = quad_sum(qh);
    float rl = rsqrtf(ql * (1.f / HH) + 1e-5f);
    float rh = rsqrtf(qh * (1.f / HH) + 1e-5f);
    int r0 = row0 + mrow + g, r1 = r0 + 8;
#pragma unroll
    for (int j = 0; j < 16; j++) {
        int jc = 8 * j + 2 * q;
        float2 lw = *(const float2*)&lnw[jc];
        float2 lb = *(const float2*)&lnb[jc];
        float2 o0, o1;
        o0.x = c[j][0] * rl * lw.x + lb.x; o0.y = c[j][1] * rl * lw.y + lb.y;
        o1.x = c[j][2] * rh * lw.x + lb.x; o1.y = c[j][3] * rh * lw.y + lb.y;
        *(float2*)&g_h[(size_t)r0 * HH + jc] = o0;
        *(float2*)&g_h[(size_t)r1 * HH + jc] = o1;
    }
}

// ---------------- edge MLP: gather-GEMM (K=256) + fused W2 reduction ----------------
__global__ void __launch_bounds__(NTH, 2) k_edgemlp(const int* __restrict__ eli, int Q,
        const float* __restrict__ W1, const float* __restrict__ b1,
        const float* __restrict__ W2, const float* __restrict__ b2,
        float* __restrict__ out) {
    __shared__ float As[2][128][24];
    __shared__ float Ws[2][8][264];
    __shared__ int sbase[128], dbase[128];
    GEMM_DECLS
    const int q0 = blockIdx.x * 128;

    if (t < 128) {
        int qq = q0 + t, s = 0, d = 0;
        if (qq < Q) { s = eli[qq]; d = eli[Q + qq]; }
        sbase[t] = s * HH; dbase[t] = d * HH;
    }
    __syncthreads();
    const float* Asrc = &g_h[(size_t)sbase[ar]];
    const float* Adst = &g_h[(size_t)dbase[ar]];

    pa = *(const float4*)(Asrc + aoff);
    pw = *(const float4*)&W1[(size_t)wr * HH + wcol];
    STAGE(0);

    const int NT = 32;
#pragma unroll 2
    for (int it = 0; it < NT; it++) {
        int cur = it & 1;
        __syncthreads();
        if (it + 1 < NT) {
            int nx = it + 1;
            const float* Ap = (nx < 16) ? (Asrc + nx * 8) : (Adst + (nx - 16) * 8);
            pa = *(const float4*)(Ap + aoff);
            pw = *(const float4*)&W1[(size_t)(nx * 8 + wr) * HH + wcol];
        }
        GEMM_COMPUTE(cur)
        if (it + 1 < NT) STAGE(cur ^ 1);
    }

    float sl = 0.f, sh = 0.f;
#pragma unroll
    for (int j = 0; j < 16; j++) {
        int jc = 8 * j + 2 * q;
        float2 bv = *(const float2*)&b1[jc];
        float2 wv = *(const float2*)&W2[jc];
        sl = fmaf(fmaxf(c[j][0] + bv.x, 0.f), wv.x, sl);
        sl = fmaf(fmaxf(c[j][1] + bv.y, 0.f), wv.y, sl);
        sh = fmaf(fmaxf(c[j][2] + bv.x, 0.f), wv.x, sh);
        sh = fmaf(fmaxf(c[j][3] + bv.y, 0.f), wv.y, sh);
    }
    sl = quad_sum(sl); sh = quad_sum(sh);
    if (q == 0) {
        float b2v = b2[0];
        int r0 = q0 + mrow + g, r1 = r0 + 8;
        if (r0 < Q) out[r0] = sl + b2v;
        if (r1 < Q) out[r1] = sh + b2v;
    }
}

// ---------------- host launch ----------------
extern "C" void kernel_launch(void* const* d_in, const int* in_sizes, int n_in,
                              void* d_out, int out_size) {
    const float* x    = (const float*)d_in[0];
    const int*   ei   = (const int*)d_in[1];
    const int*   eli  = (const int*)d_in[2];
    const float* p0Wp = (const float*)d_in[3];
    const float* p0bp = (const float*)d_in[4];
    const float* p0Wl = (const float*)d_in[5];
    const float* p0bl = (const float*)d_in[6];
    const float* p0Wr = (const float*)d_in[7];
    const float* Wp_s = (const float*)d_in[8];
    const float* bp_s = (const float*)d_in[9];
    const float* Wl_s = (const float*)d_in[10];
    const float* bl_s = (const float*)d_in[11];
    const float* Wr_s = (const float*)d_in[12];
    const float* ln_w = (const float*)d_in[13];
    const float* ln_b = (const float*)d_in[14];
    const float* eW1  = (const float*)d_in[15];
    const float* eb1  = (const float*)d_in[16];
    const float* eW2  = (const float*)d_in[17];
    const float* eb2  = (const float*)d_in[18];
    float* out = (float*)d_out;

    const int n = in_sizes[0] / 2;
    const int E = in_sizes[1] / 2;
    const int Q = in_sizes[2] / 2;

    // ---- CSR build (once) ----
    void* degp = nullptr;
    cudaGetSymbolAddress(&degp, g_deg);
    cudaMemsetAsync(degp, 0, (size_t)n * sizeof(int));
    k_hist<<<(E + 255) / 256, 256>>>(ei, E);
    const int nb = (n + SCAN_B - 1) / SCAN_B;
    k_scan1<<<nb, SCAN_B>>>(n);
    k_scan2<<<1, 1024>>>(nb);
    k_scan3<<<(n + 255) / 256, 256>>>(n, E);
    k_scatter<<<(E + 255) / 256, 256>>>(ei, E);

    // ---- layer 0 ----
    k_l0<<<(n + 255) / 256, 256>>>(x, p0Wp, p0bp, n);
    k_combine0<<<(n * 32 + 255) / 256, 256>>>(n, p0Wl, p0bl, p0Wr, ln_w, ln_b);

    // ---- layers 1..2 ----
    const int gb = (n + 127) / 128;   // 782
    const int gaggB = (n * 32 + 255) / 256;
    for (int l = 0; l < 2; l++) {
        k_proj<<<gb, NTH>>>(Wp_s + (size_t)l * HH * HH, bp_s + (size_t)l * HH);
        k_gagg<<<gaggB, 256>>>(n);
        k_combine<<<gb, NTH>>>(Wl_s + (size_t)l * HH * HH, Wr_s + (size_t)l * HH * HH,
                               bl_s + (size_t)l * HH,
                               ln_w + (size_t)(l + 1) * HH, ln_b + (size_t)(l + 1) * HH);
    }
    k_edgemlp<<<(Q + 127) / 128, NTH>>>(eli, Q, eW1, eb1, eW2, eb2, out);
}